// round 15
// baseline (speedup 1.0000x reference)
#include <cuda_runtime.h>
#include <cstdint>

#define MROWS 16384
#define CDIM  1024
#define TSEQ  2048
#define BBAT  8
#define HHEAD 16
#define SST   136   // smem row stride (words): conflict-free frag loads

// ---------------- scratch (static __device__ allocations only) ----------------
__device__ float g_r  [(size_t)MROWS*CDIM];
__device__ float g_k  [(size_t)MROWS*CDIM];
__device__ float g_v  [(size_t)MROWS*CDIM];
__device__ float g_g  [(size_t)MROWS*CDIM];
__device__ float g_wkv[(size_t)MROWS*CDIM];
__device__ float2 g_stats[BBAT*HHEAD];
__device__ float g_state_scratch[BBAT*HHEAD*64*64];
// pre-split operands, hi/lo interleaved per k-quad: uint4 = (hi01,lo01,hi23,lo23)
__device__ uint4 g_Ax[4][(size_t)MROWS*256];   // token-mixed A for r/k/v/g
__device__ uint4 g_Ws[5][(size_t)CDIM*256];    // W_r/k/v/g/o

enum { EPI_NONE=0, EPI_SIG=1, EPI_SILU=2, EPI_GOUT=3 };

__device__ __forceinline__ float sigf(float x){ return 1.0f/(1.0f+__expf(-x)); }

__device__ __forceinline__ uint32_t cvt_bf16x2(float lo, float hi){
    uint32_t r;
    asm("cvt.rn.satfinite.bf16x2.f32 %0, %1, %2;" : "=r"(r) : "f"(hi), "f"(lo));
    return r;
}
__device__ __forceinline__ void split_pack(float a0, float a1, uint32_t& hp, uint32_t& lp){
    hp = cvt_bf16x2(a0, a1);
    float h0 = __uint_as_float(hp << 16);
    float h1 = __uint_as_float(hp & 0xffff0000u);
    lp = cvt_bf16x2(a0 - h0, a1 - h1);
}

__device__ __forceinline__ void mma_bf16(float* c, const uint32_t* a, const uint32_t* b){
    asm volatile("mma.sync.aligned.m16n8k16.row.col.f32.bf16.bf16.f32 "
        "{%0,%1,%2,%3}, {%4,%5,%6,%7}, {%8,%9}, {%0,%1,%2,%3};"
        : "+f"(c[0]), "+f"(c[1]), "+f"(c[2]), "+f"(c[3])
        : "r"(a[0]), "r"(a[1]), "r"(a[2]), "r"(a[3]), "r"(b[0]), "r"(b[1]));
}

// ---------------- precompute: token-mix + bf16 split of A, all 4 mixes ---------
__global__ void xsplit_kernel(const float* __restrict__ x,
                              const float* __restrict__ mr, const float* __restrict__ mk,
                              const float* __restrict__ mv, const float* __restrict__ mg)
{
    const int idx = blockIdx.x*256 + threadIdx.x;    // 0 .. MROWS*256-1
    const int m = idx >> 8, q = idx & 255;
    const int ko = q*4;
    float4 xa = *(const float4*)(x + (size_t)m*CDIM + ko);
    float4 xs = make_float4(0,0,0,0);
    if ((m & (TSEQ-1)) != 0)
        xs = *(const float4*)(x + (size_t)(m-1)*CDIM + ko);
    const float* mixes[4] = {mr, mk, mv, mg};
    #pragma unroll
    for (int z=0; z<4; z++){
        float4 mv4 = *(const float4*)(mixes[z] + ko);
        float a0 = xa.x*mv4.x + xs.x*(1.0f-mv4.x);
        float a1 = xa.y*mv4.y + xs.y*(1.0f-mv4.y);
        float a2 = xa.z*mv4.z + xs.z*(1.0f-mv4.z);
        float a3 = xa.w*mv4.w + xs.w*(1.0f-mv4.w);
        uint32_t h0,l0,h1,l1;
        split_pack(a0, a1, h0, l0);
        split_pack(a2, a3, h1, l1);
        g_Ax[z][idx] = make_uint4(h0,l0,h1,l1);
    }
}

// ---------------- precompute: bf16 split of the 5 weight matrices --------------
__global__ void wsplit_kernel(const float* __restrict__ Wr, const float* __restrict__ Wk,
                              const float* __restrict__ Wv, const float* __restrict__ Wg,
                              const float* __restrict__ Wo)
{
    const int w = blockIdx.y;
    const float* W = (w==0)?Wr:(w==1)?Wk:(w==2)?Wv:(w==3)?Wg:Wo;
    const int idx = blockIdx.x*256 + threadIdx.x;    // 0 .. CDIM*256-1
    float4 p = *(const float4*)(W + (size_t)idx*4);
    uint32_t h0,l0,h1,l1;
    split_pack(p.x, p.y, h0, l0);
    split_pack(p.z, p.w, h1, l1);
    g_Ws[w][idx] = make_uint4(h0,l0,h1,l1);
}

// =====================================================================
// bf16x3 GEMM core (128 thr, 4 warps, warp tile 64x64, block 128x128,
// BK=16, double-buffered, static [2][8][SST] smem).
// SINGLE-BARRIER pipeline: per kt, frag-loads(buf) + store(kt+1 -> buf^1)
// + MMAs interleave freely (different buffers); one __syncthreads per kt.
// AMODE 0: A pre-mixed/pre-split (g_Ax). AMODE 1: groupnorm inline + *g_g.
// B always pre-split (g_Ws). DONORM: fused per-head L2 norm (k, v).
// =====================================================================
template<int AMODE, int EPI, bool DONORM>
__device__ __forceinline__ void gemm_core(
    uint32_t (&Ah)[2][8][SST], uint32_t (&Al)[2][8][SST],
    uint32_t (&Bh)[2][8][SST], uint32_t (&Bl)[2][8][SST],
    int bm, int bn,
    const uint4* __restrict__ Apre, const uint4* __restrict__ Wpre,
    const float* __restrict__ bias,
    const float* __restrict__ gnw, const float* __restrict__ gnb,
    float* __restrict__ out)
{
    const int tid  = threadIdx.x;
    const int lane = tid & 31;
    const int warp = tid >> 5;
    const int warpM = warp >> 1, warpN = warp & 1;

    const int lm  = tid >> 2;         // 0..31
    const int tq  = tid & 3;          // k-quad slot within stage
    const int lk4 = tq * 4;
    const int kp  = tq * 2;           // local kpair: 0,2,4,6

    float c[4][8][4];
    #pragma unroll
    for (int i=0;i<4;i++)
        #pragma unroll
        for (int j=0;j<8;j++)
            #pragma unroll
            for (int q=0;q<4;q++) c[i][j][q]=0.f;

    uint4  pa4[4], pb4[4];
    float4 paf[4];

    auto load_stage = [&](int kt){
        const int kq = kt*4 + tq;
        #pragma unroll
        for (int i=0;i<4;i++){
            const int gm = bm*128 + lm + 32*i;
            if (AMODE==0){
                pa4[i] = Apre[(size_t)gm*256 + kq];
            } else {
                const int koff = kt*16 + lk4;
                float4 w  = *(const float4*)(g_wkv + (size_t)gm*CDIM + koff);
                const int bh = (gm >> 11)*HHEAD + (koff >> 6);
                const float2 st = g_stats[bh];
                float4 gw = *(const float4*)(gnw + koff);
                float4 gb = *(const float4*)(gnb + koff);
                paf[i].x = (w.x - st.x)*st.y*gw.x + gb.x;
                paf[i].y = (w.y - st.x)*st.y*gw.y + gb.y;
                paf[i].z = (w.z - st.x)*st.y*gw.z + gb.z;
                paf[i].w = (w.w - st.x)*st.y*gw.w + gb.w;
            }
            const int gn = bn*128 + lm + 32*i;
            pb4[i] = Wpre[(size_t)gn*256 + kq];
        }
    };
    auto store_stage = [&](int buf){
        #pragma unroll
        for (int i=0;i<4;i++){
            const int m = lm + 32*i;
            if (AMODE==0){
                Ah[buf][kp  ][m]=pa4[i].x; Al[buf][kp  ][m]=pa4[i].y;
                Ah[buf][kp+1][m]=pa4[i].z; Al[buf][kp+1][m]=pa4[i].w;
            } else {
                uint32_t h0,l0,h1,l1;
                split_pack(paf[i].x, paf[i].y, h0, l0);
                split_pack(paf[i].z, paf[i].w, h1, l1);
                Ah[buf][kp  ][m]=h0; Al[buf][kp  ][m]=l0;
                Ah[buf][kp+1][m]=h1; Al[buf][kp+1][m]=l1;
            }
            Bh[buf][kp  ][m]=pb4[i].x; Bl[buf][kp  ][m]=pb4[i].y;
            Bh[buf][kp+1][m]=pb4[i].z; Bl[buf][kp+1][m]=pb4[i].w;
        }
    };

    // prologue: stage 0 in smem, stage 1 in registers
    load_stage(0);
    store_stage(0);
    __syncthreads();
    load_stage(1);

    const int g4 = lane >> 2;
    const int t4 = lane & 3;

    for (int kt=0; kt<CDIM/16; kt++){
        const int buf = kt & 1;
        // consumer frag loads from buf
        uint32_t ah[4][4], al[4][4];
        #pragma unroll
        for (int mt=0; mt<4; mt++){
            const int m = warpM*64 + mt*16 + g4;
            ah[mt][0]=Ah[buf][t4  ][m];  al[mt][0]=Al[buf][t4  ][m];
            ah[mt][1]=Ah[buf][t4  ][m+8];al[mt][1]=Al[buf][t4  ][m+8];
            ah[mt][2]=Ah[buf][t4+4][m];  al[mt][2]=Al[buf][t4+4][m];
            ah[mt][3]=Ah[buf][t4+4][m+8];al[mt][3]=Al[buf][t4+4][m+8];
        }
        uint32_t bhf[8][2], blf[8][2];
        #pragma unroll
        for (int nt=0; nt<8; nt++){
            const int n = warpN*64 + nt*8 + g4;
            bhf[nt][0]=Bh[buf][t4  ][n]; blf[nt][0]=Bl[buf][t4  ][n];
            bhf[nt][1]=Bh[buf][t4+4][n]; blf[nt][1]=Bl[buf][t4+4][n];
        }
        // store next stage into the other buffer; interleaves with MMAs below
        if (kt+1 < CDIM/16) store_stage(buf ^ 1);
        #pragma unroll
        for (int mt=0; mt<4; mt++)
            #pragma unroll
            for (int nt=0; nt<8; nt++){
                mma_bf16(c[mt][nt], ah[mt], bhf[nt]);
                mma_bf16(c[mt][nt], ah[mt], blf[nt]);
                mma_bf16(c[mt][nt], al[mt], bhf[nt]);
            }
        // prefetch registers for stage kt+2 (consumed by store at kt+1)
        if (kt+2 < CDIM/16) load_stage(kt+2);
        __syncthreads();
    }

    // ---- epilogue ----
    #pragma unroll
    for (int mt=0; mt<4; mt++){
        const int r0 = bm*128 + warpM*64 + mt*16 + g4;
        const int r1 = r0 + 8;
        #pragma unroll
        for (int nt=0; nt<8; nt++){
            const int col = bn*128 + warpN*64 + nt*8 + t4*2;
            const float2 bb = *(const float2*)(bias + col);
            c[mt][nt][0] += bb.x; c[mt][nt][1] += bb.y;
            c[mt][nt][2] += bb.x; c[mt][nt][3] += bb.y;
        }
        float sc0 = 1.0f, sc1 = 1.0f;
        if (DONORM){
            float ss0=0.f, ss1=0.f;
            #pragma unroll
            for (int nt=0; nt<8; nt++){
                ss0 = fmaf(c[mt][nt][0],c[mt][nt][0], fmaf(c[mt][nt][1],c[mt][nt][1], ss0));
                ss1 = fmaf(c[mt][nt][2],c[mt][nt][2], fmaf(c[mt][nt][3],c[mt][nt][3], ss1));
            }
            ss0 += __shfl_xor_sync(0xffffffffu, ss0, 1);
            ss0 += __shfl_xor_sync(0xffffffffu, ss0, 2);
            ss1 += __shfl_xor_sync(0xffffffffu, ss1, 1);
            ss1 += __shfl_xor_sync(0xffffffffu, ss1, 2);
            sc0 = 1.0f/fmaxf(sqrtf(ss0), 1e-12f);
            sc1 = 1.0f/fmaxf(sqrtf(ss1), 1e-12f);
        }
        #pragma unroll
        for (int nt=0; nt<8; nt++){
            const int col = bn*128 + warpN*64 + nt*8 + t4*2;
            float v0 = c[mt][nt][0], v1 = c[mt][nt][1];
            float v2 = c[mt][nt][2], v3 = c[mt][nt][3];
            if (DONORM){ v0*=sc0; v1*=sc0; v2*=sc1; v3*=sc1; }
            if (EPI==EPI_SIG){ v0=sigf(v0); v1=sigf(v1); v2=sigf(v2); v3=sigf(v3); }
            else if (EPI==EPI_SILU){ v0*=sigf(v0); v1*=sigf(v1); v2*=sigf(v2); v3*=sigf(v3); }
            else if (EPI==EPI_GOUT){
                float2 g0 = *(const float2*)(g_g + (size_t)r0*CDIM + col);
                float2 g1 = *(const float2*)(g_g + (size_t)r1*CDIM + col);
                v0*=g0.x; v1*=g0.y; v2*=g1.x; v3*=g1.y;
            }
            *(float2*)(out + (size_t)r0*CDIM + col) = make_float2(v0,v1);
            *(float2*)(out + (size_t)r1*CDIM + col) = make_float2(v2,v3);
        }
    }
}

// ---------------- scan body: 1 CTA (128 thr) per (b,h) -------------------------
// R7-proven structure + validated fast-math trims (kept; cost-neutral).
__device__ __forceinline__ void scan_body(
    int bh, const float* __restrict__ decay, const float* __restrict__ eta,
    float* __restrict__ state_out)
{
    __shared__ __align__(16) float sk[2][64], sr[2][64], sv[2][64];
    __shared__ float red[2][4];
    __shared__ double redd[4][2];

    const int b = bh >> 4, h = bh & 15;
    const int t_ = threadIdx.x;
    const int row = t_ >> 1, half = t_ & 1;
    const int lane = t_ & 31, wid = t_ >> 5;
    const int koff = half*32;

    float S[32];
    #pragma unroll
    for (int j=0;j<32;j++) S[j]=0.f;
    float c = 1.0f;
    float ns = 0.f;
    const float dec = 1.0f/(1.0f+expf(-decay[h]));
    const float et  = 1.0f/(1.0f+expf(-eta[h]));
    const float maxn = 16.0f;
    double wsum = 0.0, wsq = 0.0;

    const size_t base = (size_t)b*TSEQ*CDIM + (size_t)h*64;
    const float* kp = g_k + base;
    const float* rp = g_r + base;
    const float* vp = g_v + base;
    float*       op = g_wkv + base;

    if (t_ < 64){ sk[0][t_] = kp[t_]; sv[0][t_] = vp[t_]; }
    else        { sr[0][t_-64] = rp[t_-64]; }
    float nk=0.f, nr=0.f, nv=0.f;
    if (t_ < 64){ nk = kp[CDIM+t_]; nv = vp[CDIM+t_]; }
    else        { nr = rp[CDIM+t_-64]; }
    __syncthreads();

    for (int t=0; t<TSEQ; t++){
        const int buf  = t & 1;
        const int nbuf = buf ^ 1;
        if (t+1 < TSEQ){
            if (t_ < 64){ sk[nbuf][t_]=nk; sv[nbuf][t_]=nv; }
            else        { sr[nbuf][t_-64]=nr; }
        }
        if (t+2 < TSEQ){
            if (t_ < 64){ nk = kp[2*CDIM+t_]; nv = vp[2*CDIM+t_]; }
            else        { nr = rp[2*CDIM+t_-64]; }
        }
        const float4* k4 = (const float4*)(&sk[buf][koff]);
        float q0=0,q1=0,q2=0,q3=0;
        #pragma unroll
        for (int j=0;j<8;j++){
            float4 kv = k4[j];
            q0 = fmaf(S[4*j+0], kv.x, q0);
            q1 = fmaf(S[4*j+1], kv.y, q1);
            q2 = fmaf(S[4*j+2], kv.z, q2);
            q3 = fmaf(S[4*j+3], kv.w, q3);
        }
        float qp = (q0+q1)+(q2+q3);
        qp += __shfl_xor_sync(0xffffffffu, qp, 1);
        const float vi   = sv[buf][row];
        const float err  = c*qp - vi;
        const float c1   = dec*c;
        const float coef = __fdividef(et*err, c1);
        const bool exact = ((t & 31) == 31);
        #pragma unroll
        for (int j=0;j<8;j++){
            float4 kv = k4[j];
            S[4*j+0] = fmaf(-coef, kv.x, S[4*j+0]);
            S[4*j+1] = fmaf(-coef, kv.y, S[4*j+1]);
            S[4*j+2] = fmaf(-coef, kv.z, S[4*j+2]);
            S[4*j+3] = fmaf(-coef, kv.w, S[4*j+3]);
        }
        float val;
        if (exact){
            float u0=0,u1=0,u2=0,u3=0;
            #pragma unroll
            for (int j=0;j<8;j++){
                u0 = fmaf(S[4*j+0],S[4*j+0],u0);
                u1 = fmaf(S[4*j+1],S[4*j+1],u1);
                u2 = fmaf(S[4*j+2],S[4*j+2],u2);
                u3 = fmaf(S[4*j+3],S[4*j+3],u3);
            }
            val = (u0+u1)+(u2+u3);
        } else {
            val = 0.5f*fmaf(coef, coef, -2.0f*coef*qp);
        }
        const float4* r4 = (const float4*)(&sr[buf][koff]);
        float w0=0,w1=0,w2=0,w3=0;
        #pragma unroll
        for (int j=0;j<8;j++){
            float4 rv = r4[j];
            w0 = fmaf(S[4*j+0], rv.x, w0);
            w1 = fmaf(S[4*j+1], rv.y, w1);
            w2 = fmaf(S[4*j+2], rv.z, w2);
            w3 = fmaf(S[4*j+3], rv.w, w3);
        }
        #pragma unroll
        for (int o=16;o;o>>=1) val += __shfl_xor_sync(0xffffffffu, val, o);
        if (lane==0) red[buf][wid]=val;
        float wpart = (w0+w1)+(w2+w3);
        wpart += __shfl_xor_sync(0xffffffffu, wpart, 1);
        __syncthreads();
        const float tot = red[buf][0]+red[buf][1]+red[buf][2]+red[buf][3];
        ns = exact ? tot : fmaxf(ns + tot, 0.f);
        // clamp: nrm = c1*sqrt(ns) > maxn  <=>  c1^2*ns > maxn^2
        c = (c1*c1*ns > maxn*maxn) ? maxn*rsqrtf(ns) : c1;
        const float wv = c*wpart;
        if (half==0) op[row] = wv;
        wsum += (double)wv;
        wsq  += (double)wv*(double)wv;
        if (exact){
            #pragma unroll
            for (int j=0;j<32;j++) S[j]*=c;
            ns *= c*c;
            c = 1.0f;
        }
        kp += CDIM; rp += CDIM; vp += CDIM; op += CDIM;
    }
    double a1=wsum, a2=wsq;
    #pragma unroll
    for (int o=16;o;o>>=1){
        a1 += __shfl_xor_sync(0xffffffffu, a1, o);
        a2 += __shfl_xor_sync(0xffffffffu, a2, o);
    }
    if (lane==0){ redd[wid][0]=a1; redd[wid][1]=a2; }
    __syncthreads();
    if (t_==0){
        const double t1 = redd[0][0]+redd[1][0]+redd[2][0]+redd[3][0];
        const double t2 = redd[0][1]+redd[1][1]+redd[2][1]+redd[3][1];
        const double cnt = 2.0*(double)TSEQ*64.0;
        const double mean = t1 / cnt;
        const double var  = t2 / cnt - mean*mean;
        g_stats[bh] = make_float2((float)mean, (float)(1.0/sqrt(var + 1e-5)));
    }
    float* so = state_out ? state_out : g_state_scratch;
    #pragma unroll
    for (int j=0;j<32;j++)
        so[(size_t)bh*4096 + (size_t)row*64 + koff + j] = c*S[j];
}

// ---------------- kernels ------------------------------------------------------

__global__ __launch_bounds__(128, 2)
void proj_kernel(const float* __restrict__ b_r, const float* __restrict__ b_k,
                 const float* __restrict__ b_v)
{
    __shared__ uint32_t Ah[2][8][SST], Al[2][8][SST];
    __shared__ uint32_t Bh[2][8][SST], Bl[2][8][SST];
    const int bm = blockIdx.y, bn = blockIdx.x, z = blockIdx.z;
    if (z==0)
        gemm_core<0,EPI_SIG, false>(Ah,Al,Bh,Bl,bm,bn, g_Ax[0], g_Ws[0], b_r, nullptr,nullptr, g_r);
    else if (z==1)
        gemm_core<0,EPI_NONE,true >(Ah,Al,Bh,Bl,bm,bn, g_Ax[1], g_Ws[1], b_k, nullptr,nullptr, g_k);
    else
        gemm_core<0,EPI_NONE,true >(Ah,Al,Bh,Bl,bm,bn, g_Ax[2], g_Ws[2], b_v, nullptr,nullptr, g_v);
}

// merged: scan (CTAs 0..127) + g projection (CTAs 128..1151)
__global__ __launch_bounds__(128, 2)
void scan_g_kernel(const float* __restrict__ b_g,
                   const float* __restrict__ decay, const float* __restrict__ eta,
                   float* __restrict__ state_out)
{
    __shared__ uint32_t Ah[2][8][SST], Al[2][8][SST];
    __shared__ uint32_t Bh[2][8][SST], Bl[2][8][SST];
    if (blockIdx.x < 128){
        scan_body(blockIdx.x, decay, eta, state_out);
    } else {
        const int bi = blockIdx.x - 128;
        gemm_core<0,EPI_SILU,false>(Ah,Al,Bh,Bl, bi>>3, bi&7, g_Ax[3], g_Ws[3], b_g,
                                    nullptr,nullptr, g_g);
    }
}

__global__ __launch_bounds__(128, 2)
void outproj_kernel(const float* __restrict__ b_o,
                    const float* __restrict__ gnw, const float* __restrict__ gnb,
                    float* __restrict__ out)
{
    __shared__ uint32_t Ah[2][8][SST], Al[2][8][SST];
    __shared__ uint32_t Bh[2][8][SST], Bl[2][8][SST];
    gemm_core<1,EPI_GOUT,false>(Ah,Al,Bh,Bl, blockIdx.y, blockIdx.x,
                                nullptr, g_Ws[4], b_o, gnw, gnb, out);
}

__global__ void lastx_kernel(const float* __restrict__ x, float* __restrict__ outp)
{
    const int i = blockIdx.x*blockDim.x + threadIdx.x;
    if (i >= BBAT*CDIM) return;
    const int b  = i >> 10;
    const int cc = i & (CDIM-1);
    outp[i] = x[((size_t)b*TSEQ + (TSEQ-1))*CDIM + cc];
}

// ---------------- launch --------------------------------------------------------
extern "C" void kernel_launch(void* const* d_in, const int* in_sizes, int n_in,
                              void* d_out, int out_size)
{
    const float* x    = (const float*)d_in[0];
    const float* W_r  = (const float*)d_in[1];
    const float* b_r  = (const float*)d_in[2];
    const float* W_k  = (const float*)d_in[3];
    const float* b_k  = (const float*)d_in[4];
    const float* W_v  = (const float*)d_in[5];
    const float* b_v  = (const float*)d_in[6];
    const float* W_g  = (const float*)d_in[7];
    const float* b_g  = (const float*)d_in[8];
    const float* W_o  = (const float*)d_in[9];
    const float* b_o  = (const float*)d_in[10];
    const float* decay= (const float*)d_in[11];
    const float* eta  = (const float*)d_in[12];
    const float* mixr = (const float*)d_in[13];
    const float* mixk = (const float*)d_in[14];
    const float* mixv = (const float*)d_in[15];
    const float* mixg = (const float*)d_in[16];
    const float* gnw  = (const float*)d_in[17];
    const float* gnb  = (const float*)d_in[18];
    float* out = (float*)d_out;

    const int MAIN  = MROWS*CDIM;
    const int STATE = BBAT*HHEAD*64*64;
    const int LASTX = BBAT*CDIM;
    const bool full = out_size >= MAIN + STATE + LASTX;

    if (full) lastx_kernel<<<32,256>>>(x, out + MAIN + STATE);
    wsplit_kernel<<<dim3(1024,5),256>>>(W_r, W_k, W_v, W_g, W_o);
    xsplit_kernel<<<16384,256>>>(x, mixr, mixk, mixv, mixg);
    proj_kernel<<<dim3(8,128,3),128>>>(b_r, b_k, b_v);
    scan_g_kernel<<<128+1024,128>>>(b_g, decay, eta, full ? (out + MAIN) : nullptr);
    outproj_kernel<<<dim3(8,128),128>>>(b_o, gnw, gnb, out);
}

// round 16
// speedup vs baseline: 1.0258x; 1.0258x over previous
#include <cuda_runtime.h>
#include <cstdint>

#define MROWS 16384
#define CDIM  1024
#define TSEQ  2048
#define BBAT  8
#define HHEAD 16
#define SST   136   // smem row stride (words): conflict-free frag loads

// ---------------- scratch (static __device__ allocations only) ----------------
__device__ float g_r  [(size_t)MROWS*CDIM];
__device__ float g_k  [(size_t)MROWS*CDIM];
__device__ float g_v  [(size_t)MROWS*CDIM];
__device__ float g_g  [(size_t)MROWS*CDIM];
__device__ float g_wkv[(size_t)MROWS*CDIM];
__device__ float2 g_stats[BBAT*HHEAD];
__device__ float g_state_scratch[BBAT*HHEAD*64*64];
// pre-split operands, hi/lo interleaved per k-quad: uint4 = (hi01,lo01,hi23,lo23)
__device__ uint4 g_Ax[4][(size_t)MROWS*256];   // token-mixed A for r/k/v/g
__device__ uint4 g_Ws[5][(size_t)CDIM*256];    // W_r/k/v/g/o

enum { EPI_NONE=0, EPI_SIG=1, EPI_SILU=2, EPI_GOUT=3 };

__device__ __forceinline__ float sigf(float x){ return 1.0f/(1.0f+__expf(-x)); }

__device__ __forceinline__ uint32_t cvt_bf16x2(float lo, float hi){
    uint32_t r;
    asm("cvt.rn.satfinite.bf16x2.f32 %0, %1, %2;" : "=r"(r) : "f"(hi), "f"(lo));
    return r;
}
__device__ __forceinline__ void split_pack(float a0, float a1, uint32_t& hp, uint32_t& lp){
    hp = cvt_bf16x2(a0, a1);
    float h0 = __uint_as_float(hp << 16);
    float h1 = __uint_as_float(hp & 0xffff0000u);
    lp = cvt_bf16x2(a0 - h0, a1 - h1);
}

__device__ __forceinline__ void mma_bf16(float* c, const uint32_t* a, const uint32_t* b){
    asm volatile("mma.sync.aligned.m16n8k16.row.col.f32.bf16.bf16.f32 "
        "{%0,%1,%2,%3}, {%4,%5,%6,%7}, {%8,%9}, {%0,%1,%2,%3};"
        : "+f"(c[0]), "+f"(c[1]), "+f"(c[2]), "+f"(c[3])
        : "r"(a[0]), "r"(a[1]), "r"(a[2]), "r"(a[3]), "r"(b[0]), "r"(b[1]));
}

// ---------------- precompute: token-mix + bf16 split of A, all 4 mixes ---------
__global__ void xsplit_kernel(const float* __restrict__ x,
                              const float* __restrict__ mr, const float* __restrict__ mk,
                              const float* __restrict__ mv, const float* __restrict__ mg)
{
    const int idx = blockIdx.x*256 + threadIdx.x;    // 0 .. MROWS*256-1
    const int m = idx >> 8, q = idx & 255;
    const int ko = q*4;
    float4 xa = *(const float4*)(x + (size_t)m*CDIM + ko);
    float4 xs = make_float4(0,0,0,0);
    if ((m & (TSEQ-1)) != 0)
        xs = *(const float4*)(x + (size_t)(m-1)*CDIM + ko);
    const float* mixes[4] = {mr, mk, mv, mg};
    #pragma unroll
    for (int z=0; z<4; z++){
        float4 mv4 = *(const float4*)(mixes[z] + ko);
        float a0 = xa.x*mv4.x + xs.x*(1.0f-mv4.x);
        float a1 = xa.y*mv4.y + xs.y*(1.0f-mv4.y);
        float a2 = xa.z*mv4.z + xs.z*(1.0f-mv4.z);
        float a3 = xa.w*mv4.w + xs.w*(1.0f-mv4.w);
        uint32_t h0,l0,h1,l1;
        split_pack(a0, a1, h0, l0);
        split_pack(a2, a3, h1, l1);
        g_Ax[z][idx] = make_uint4(h0,l0,h1,l1);
    }
}

// ---------------- precompute: bf16 split of the 5 weight matrices --------------
__global__ void wsplit_kernel(const float* __restrict__ Wr, const float* __restrict__ Wk,
                              const float* __restrict__ Wv, const float* __restrict__ Wg,
                              const float* __restrict__ Wo)
{
    const int w = blockIdx.y;
    const float* W = (w==0)?Wr:(w==1)?Wk:(w==2)?Wv:(w==3)?Wg:Wo;
    const int idx = blockIdx.x*256 + threadIdx.x;    // 0 .. CDIM*256-1
    float4 p = *(const float4*)(W + (size_t)idx*4);
    uint32_t h0,l0,h1,l1;
    split_pack(p.x, p.y, h0, l0);
    split_pack(p.z, p.w, h1, l1);
    g_Ws[w][idx] = make_uint4(h0,l0,h1,l1);
}

// =====================================================================
// bf16x3 GEMM core (R11/R14-proven: 128 thr, 4 warps, warp tile 64x64,
// block 128x128, BK=16, double-buffered, static [2][8][SST] smem).
// AMODE 0: A pre-mixed/pre-split (g_Ax) -> loader is pure LDG.128 + STS.
// AMODE 1: A = groupnorm(g_wkv) computed+split inline; epilogue *g_g.
// B always pre-split (g_Ws). DONORM: fused per-head L2 norm (k, v).
// =====================================================================
template<int AMODE, int EPI, bool DONORM>
__device__ __forceinline__ void gemm_core(
    uint32_t (&Ah)[2][8][SST], uint32_t (&Al)[2][8][SST],
    uint32_t (&Bh)[2][8][SST], uint32_t (&Bl)[2][8][SST],
    int bm, int bn,
    const uint4* __restrict__ Apre, const uint4* __restrict__ Wpre,
    const float* __restrict__ bias,
    const float* __restrict__ gnw, const float* __restrict__ gnb,
    float* __restrict__ out)
{
    const int tid  = threadIdx.x;
    const int lane = tid & 31;
    const int warp = tid >> 5;
    const int warpM = warp >> 1, warpN = warp & 1;

    const int lm  = tid >> 2;         // 0..31
    const int tq  = tid & 3;          // k-quad slot within stage
    const int lk4 = tq * 4;
    const int kp  = tq * 2;           // local kpair: 0,2,4,6

    float c[4][8][4];
    #pragma unroll
    for (int i=0;i<4;i++)
        #pragma unroll
        for (int j=0;j<8;j++)
            #pragma unroll
            for (int q=0;q<4;q++) c[i][j][q]=0.f;

    uint4  pa4[4], pb4[4];
    float4 paf[4];

    auto load_stage = [&](int kt){
        const int kq = kt*4 + tq;
        #pragma unroll
        for (int i=0;i<4;i++){
            const int gm = bm*128 + lm + 32*i;
            if (AMODE==0){
                pa4[i] = Apre[(size_t)gm*256 + kq];
            } else {
                const int koff = kt*16 + lk4;
                float4 w  = *(const float4*)(g_wkv + (size_t)gm*CDIM + koff);
                const int bh = (gm >> 11)*HHEAD + (koff >> 6);
                const float2 st = g_stats[bh];
                float4 gw = *(const float4*)(gnw + koff);
                float4 gb = *(const float4*)(gnb + koff);
                paf[i].x = (w.x - st.x)*st.y*gw.x + gb.x;
                paf[i].y = (w.y - st.x)*st.y*gw.y + gb.y;
                paf[i].z = (w.z - st.x)*st.y*gw.z + gb.z;
                paf[i].w = (w.w - st.x)*st.y*gw.w + gb.w;
            }
            const int gn = bn*128 + lm + 32*i;
            pb4[i] = Wpre[(size_t)gn*256 + kq];
        }
    };
    auto store_stage = [&](int buf){
        #pragma unroll
        for (int i=0;i<4;i++){
            const int m = lm + 32*i;
            if (AMODE==0){
                Ah[buf][kp  ][m]=pa4[i].x; Al[buf][kp  ][m]=pa4[i].y;
                Ah[buf][kp+1][m]=pa4[i].z; Al[buf][kp+1][m]=pa4[i].w;
            } else {
                uint32_t h0,l0,h1,l1;
                split_pack(paf[i].x, paf[i].y, h0, l0);
                split_pack(paf[i].z, paf[i].w, h1, l1);
                Ah[buf][kp  ][m]=h0; Al[buf][kp  ][m]=l0;
                Ah[buf][kp+1][m]=h1; Al[buf][kp+1][m]=l1;
            }
            Bh[buf][kp  ][m]=pb4[i].x; Bl[buf][kp  ][m]=pb4[i].y;
            Bh[buf][kp+1][m]=pb4[i].z; Bl[buf][kp+1][m]=pb4[i].w;
        }
    };

    load_stage(0);

    const int g4 = lane >> 2;
    const int t4 = lane & 3;

    for (int kt=0; kt<CDIM/16; kt++){
        const int buf = kt & 1;
        store_stage(buf);
        __syncthreads();
        if (kt+1 < CDIM/16) load_stage(kt+1);

        uint32_t ah[4][4], al[4][4];
        #pragma unroll
        for (int mt=0; mt<4; mt++){
            const int m = warpM*64 + mt*16 + g4;
            ah[mt][0]=Ah[buf][t4  ][m];  al[mt][0]=Al[buf][t4  ][m];
            ah[mt][1]=Ah[buf][t4  ][m+8];al[mt][1]=Al[buf][t4  ][m+8];
            ah[mt][2]=Ah[buf][t4+4][m];  al[mt][2]=Al[buf][t4+4][m];
            ah[mt][3]=Ah[buf][t4+4][m+8];al[mt][3]=Al[buf][t4+4][m+8];
        }
        uint32_t bhf[8][2], blf[8][2];
        #pragma unroll
        for (int nt=0; nt<8; nt++){
            const int n = warpN*64 + nt*8 + g4;
            bhf[nt][0]=Bh[buf][t4  ][n]; blf[nt][0]=Bl[buf][t4  ][n];
            bhf[nt][1]=Bh[buf][t4+4][n]; blf[nt][1]=Bl[buf][t4+4][n];
        }
        #pragma unroll
        for (int mt=0; mt<4; mt++)
            #pragma unroll
            for (int nt=0; nt<8; nt++){
                mma_bf16(c[mt][nt], ah[mt], bhf[nt]);
                mma_bf16(c[mt][nt], ah[mt], blf[nt]);
                mma_bf16(c[mt][nt], al[mt], bhf[nt]);
            }
        __syncthreads();
    }

    // ---- epilogue ----
    #pragma unroll
    for (int mt=0; mt<4; mt++){
        const int r0 = bm*128 + warpM*64 + mt*16 + g4;
        const int r1 = r0 + 8;
        #pragma unroll
        for (int nt=0; nt<8; nt++){
            const int col = bn*128 + warpN*64 + nt*8 + t4*2;
            const float2 bb = *(const float2*)(bias + col);
            c[mt][nt][0] += bb.x; c[mt][nt][1] += bb.y;
            c[mt][nt][2] += bb.x; c[mt][nt][3] += bb.y;
        }
        float sc0 = 1.0f, sc1 = 1.0f;
        if (DONORM){
            float ss0=0.f, ss1=0.f;
            #pragma unroll
            for (int nt=0; nt<8; nt++){
                ss0 = fmaf(c[mt][nt][0],c[mt][nt][0], fmaf(c[mt][nt][1],c[mt][nt][1], ss0));
                ss1 = fmaf(c[mt][nt][2],c[mt][nt][2], fmaf(c[mt][nt][3],c[mt][nt][3], ss1));
            }
            ss0 += __shfl_xor_sync(0xffffffffu, ss0, 1);
            ss0 += __shfl_xor_sync(0xffffffffu, ss0, 2);
            ss1 += __shfl_xor_sync(0xffffffffu, ss1, 1);
            ss1 += __shfl_xor_sync(0xffffffffu, ss1, 2);
            sc0 = 1.0f/fmaxf(sqrtf(ss0), 1e-12f);
            sc1 = 1.0f/fmaxf(sqrtf(ss1), 1e-12f);
        }
        #pragma unroll
        for (int nt=0; nt<8; nt++){
            const int col = bn*128 + warpN*64 + nt*8 + t4*2;
            float v0 = c[mt][nt][0], v1 = c[mt][nt][1];
            float v2 = c[mt][nt][2], v3 = c[mt][nt][3];
            if (DONORM){ v0*=sc0; v1*=sc0; v2*=sc1; v3*=sc1; }
            if (EPI==EPI_SIG){ v0=sigf(v0); v1=sigf(v1); v2=sigf(v2); v3=sigf(v3); }
            else if (EPI==EPI_SILU){ v0*=sigf(v0); v1*=sigf(v1); v2*=sigf(v2); v3*=sigf(v3); }
            else if (EPI==EPI_GOUT){
                float2 g0 = *(const float2*)(g_g + (size_t)r0*CDIM + col);
                float2 g1 = *(const float2*)(g_g + (size_t)r1*CDIM + col);
                v0*=g0.x; v1*=g0.y; v2*=g1.x; v3*=g1.y;
            }
            *(float2*)(out + (size_t)r0*CDIM + col) = make_float2(v0,v1);
            *(float2*)(out + (size_t)r1*CDIM + col) = make_float2(v2,v3);
        }
    }
}

// ---------------- scan body: 1 CTA (128 thr) per (b,h) -------------------------
// R7-proven structure + validated fast-math trims.
__device__ __forceinline__ void scan_body(
    int bh, const float* __restrict__ decay, const float* __restrict__ eta,
    float* __restrict__ state_out)
{
    __shared__ __align__(16) float sk[2][64], sr[2][64], sv[2][64];
    __shared__ float red[2][4];
    __shared__ double redd[4][2];

    const int b = bh >> 4, h = bh & 15;
    const int t_ = threadIdx.x;
    const int row = t_ >> 1, half = t_ & 1;
    const int lane = t_ & 31, wid = t_ >> 5;
    const int koff = half*32;

    float S[32];
    #pragma unroll
    for (int j=0;j<32;j++) S[j]=0.f;
    float c = 1.0f;
    float ns = 0.f;
    const float dec = 1.0f/(1.0f+expf(-decay[h]));
    const float et  = 1.0f/(1.0f+expf(-eta[h]));
    const float maxn = 16.0f;
    double wsum = 0.0, wsq = 0.0;

    const size_t base = (size_t)b*TSEQ*CDIM + (size_t)h*64;
    const float* kp = g_k + base;
    const float* rp = g_r + base;
    const float* vp = g_v + base;
    float*       op = g_wkv + base;

    if (t_ < 64){ sk[0][t_] = kp[t_]; sv[0][t_] = vp[t_]; }
    else        { sr[0][t_-64] = rp[t_-64]; }
    float nk=0.f, nr=0.f, nv=0.f;
    if (t_ < 64){ nk = kp[CDIM+t_]; nv = vp[CDIM+t_]; }
    else        { nr = rp[CDIM+t_-64]; }
    __syncthreads();

    for (int t=0; t<TSEQ; t++){
        const int buf  = t & 1;
        const int nbuf = buf ^ 1;
        if (t+1 < TSEQ){
            if (t_ < 64){ sk[nbuf][t_]=nk; sv[nbuf][t_]=nv; }
            else        { sr[nbuf][t_-64]=nr; }
        }
        if (t+2 < TSEQ){
            if (t_ < 64){ nk = kp[2*CDIM+t_]; nv = vp[2*CDIM+t_]; }
            else        { nr = rp[2*CDIM+t_-64]; }
        }
        const float4* k4 = (const float4*)(&sk[buf][koff]);
        float q0=0,q1=0,q2=0,q3=0;
        #pragma unroll
        for (int j=0;j<8;j++){
            float4 kv = k4[j];
            q0 = fmaf(S[4*j+0], kv.x, q0);
            q1 = fmaf(S[4*j+1], kv.y, q1);
            q2 = fmaf(S[4*j+2], kv.z, q2);
            q3 = fmaf(S[4*j+3], kv.w, q3);
        }
        float qp = (q0+q1)+(q2+q3);
        qp += __shfl_xor_sync(0xffffffffu, qp, 1);
        const float vi   = sv[buf][row];
        const float err  = c*qp - vi;
        const float c1   = dec*c;
        const float coef = __fdividef(et*err, c1);
        const bool exact = ((t & 31) == 31);
        #pragma unroll
        for (int j=0;j<8;j++){
            float4 kv = k4[j];
            S[4*j+0] = fmaf(-coef, kv.x, S[4*j+0]);
            S[4*j+1] = fmaf(-coef, kv.y, S[4*j+1]);
            S[4*j+2] = fmaf(-coef, kv.z, S[4*j+2]);
            S[4*j+3] = fmaf(-coef, kv.w, S[4*j+3]);
        }
        float val;
        if (exact){
            float u0=0,u1=0,u2=0,u3=0;
            #pragma unroll
            for (int j=0;j<8;j++){
                u0 = fmaf(S[4*j+0],S[4*j+0],u0);
                u1 = fmaf(S[4*j+1],S[4*j+1],u1);
                u2 = fmaf(S[4*j+2],S[4*j+2],u2);
                u3 = fmaf(S[4*j+3],S[4*j+3],u3);
            }
            val = (u0+u1)+(u2+u3);
        } else {
            val = 0.5f*fmaf(coef, coef, -2.0f*coef*qp);
        }
        const float4* r4 = (const float4*)(&sr[buf][koff]);
        float w0=0,w1=0,w2=0,w3=0;
        #pragma unroll
        for (int j=0;j<8;j++){
            float4 rv = r4[j];
            w0 = fmaf(S[4*j+0], rv.x, w0);
            w1 = fmaf(S[4*j+1], rv.y, w1);
            w2 = fmaf(S[4*j+2], rv.z, w2);
            w3 = fmaf(S[4*j+3], rv.w, w3);
        }
        #pragma unroll
        for (int o=16;o;o>>=1) val += __shfl_xor_sync(0xffffffffu, val, o);
        if (lane==0) red[buf][wid]=val;
        float wpart = (w0+w1)+(w2+w3);
        wpart += __shfl_xor_sync(0xffffffffu, wpart, 1);
        __syncthreads();
        const float tot = red[buf][0]+red[buf][1]+red[buf][2]+red[buf][3];
        ns = exact ? tot : fmaxf(ns + tot, 0.f);
        // clamp: nrm = c1*sqrt(ns) > maxn  <=>  c1^2*ns > maxn^2
        c = (c1*c1*ns > maxn*maxn) ? maxn*rsqrtf(ns) : c1;
        const float wv = c*wpart;
        if (half==0) op[row] = wv;
        wsum += (double)wv;
        wsq  += (double)wv*(double)wv;
        if (exact){
            #pragma unroll
            for (int j=0;j<32;j++) S[j]*=c;
            ns *= c*c;
            c = 1.0f;
        }
        kp += CDIM; rp += CDIM; vp += CDIM; op += CDIM;
    }
    double a1=wsum, a2=wsq;
    #pragma unroll
    for (int o=16;o;o>>=1){
        a1 += __shfl_xor_sync(0xffffffffu, a1, o);
        a2 += __shfl_xor_sync(0xffffffffu, a2, o);
    }
    if (lane==0){ redd[wid][0]=a1; redd[wid][1]=a2; }
    __syncthreads();
    if (t_==0){
        const double t1 = redd[0][0]+redd[1][0]+redd[2][0]+redd[3][0];
        const double t2 = redd[0][1]+redd[1][1]+redd[2][1]+redd[3][1];
        const double cnt = 2.0*(double)TSEQ*64.0;
        const double mean = t1 / cnt;
        const double var  = t2 / cnt - mean*mean;
        g_stats[bh] = make_float2((float)mean, (float)(1.0/sqrt(var + 1e-5)));
    }
    float* so = state_out ? state_out : g_state_scratch;
    #pragma unroll
    for (int j=0;j<32;j++)
        so[(size_t)bh*4096 + (size_t)row*64 + koff + j] = c*S[j];
}

// ---------------- kernels ------------------------------------------------------

__global__ __launch_bounds__(128, 2)
void proj_kernel(const float* __restrict__ b_r, const float* __restrict__ b_k,
                 const float* __restrict__ b_v)
{
    __shared__ uint32_t Ah[2][8][SST], Al[2][8][SST];
    __shared__ uint32_t Bh[2][8][SST], Bl[2][8][SST];
    const int bm = blockIdx.y, bn = blockIdx.x, z = blockIdx.z;
    if (z==0)
        gemm_core<0,EPI_SIG, false>(Ah,Al,Bh,Bl,bm,bn, g_Ax[0], g_Ws[0], b_r, nullptr,nullptr, g_r);
    else if (z==1)
        gemm_core<0,EPI_NONE,true >(Ah,Al,Bh,Bl,bm,bn, g_Ax[1], g_Ws[1], b_k, nullptr,nullptr, g_k);
    else
        gemm_core<0,EPI_NONE,true >(Ah,Al,Bh,Bl,bm,bn, g_Ax[2], g_Ws[2], b_v, nullptr,nullptr, g_v);
}

// merged: scan + g projection, grid = 1152 CTAs.
// Scan CTAs live at bids {0..63} U {148..211}: since classic placement maps
// bid -> LUT[bid % 148], bids b and b+148 share an SM -> each scan SM hosts
// TWO scan CTAs whose warps interleave on the SMSPs (latency hiding for the
// serial per-step chain). g-projection CTAs fill all remaining bids.
__global__ __launch_bounds__(128, 2)
void scan_g_kernel(const float* __restrict__ b_g,
                   const float* __restrict__ decay, const float* __restrict__ eta,
                   float* __restrict__ state_out)
{
    __shared__ uint32_t Ah[2][8][SST], Al[2][8][SST];
    __shared__ uint32_t Bh[2][8][SST], Bl[2][8][SST];
    const int bid = blockIdx.x;
    const bool is_scan = (bid < 64) || (bid >= 148 && bid < 212);
    if (is_scan){
        const int si = (bid < 64) ? bid : 64 + (bid - 148);
        scan_body(si, decay, eta, state_out);
    } else {
        const int gi = (bid < 148) ? (bid - 64) : (84 + (bid - 212));
        gemm_core<0,EPI_SILU,false>(Ah,Al,Bh,Bl, gi>>3, gi&7, g_Ax[3], g_Ws[3], b_g,
                                    nullptr,nullptr, g_g);
    }
}

__global__ __launch_bounds__(128, 2)
void outproj_kernel(const float* __restrict__ b_o,
                    const float* __restrict__ gnw, const float* __restrict__ gnb,
                    float* __restrict__ out)
{
    __shared__ uint32_t Ah[2][8][SST], Al[2][8][SST];
    __shared__ uint32_t Bh[2][8][SST], Bl[2][8][SST];
    gemm_core<1,EPI_GOUT,false>(Ah,Al,Bh,Bl, blockIdx.y, blockIdx.x,
                                nullptr, g_Ws[4], b_o, gnw, gnb, out);
}

__global__ void lastx_kernel(const float* __restrict__ x, float* __restrict__ outp)
{
    const int i = blockIdx.x*blockDim.x + threadIdx.x;
    if (i >= BBAT*CDIM) return;
    const int b  = i >> 10;
    const int cc = i & (CDIM-1);
    outp[i] = x[((size_t)b*TSEQ + (TSEQ-1))*CDIM + cc];
}

// ---------------- launch --------------------------------------------------------
extern "C" void kernel_launch(void* const* d_in, const int* in_sizes, int n_in,
                              void* d_out, int out_size)
{
    const float* x    = (const float*)d_in[0];
    const float* W_r  = (const float*)d_in[1];
    const float* b_r  = (const float*)d_in[2];
    const float* W_k  = (const float*)d_in[3];
    const float* b_k  = (const float*)d_in[4];
    const float* W_v  = (const float*)d_in[5];
    const float* b_v  = (const float*)d_in[6];
    const float* W_g  = (const float*)d_in[7];
    const float* b_g  = (const float*)d_in[8];
    const float* W_o  = (const float*)d_in[9];
    const float* b_o  = (const float*)d_in[10];
    const float* decay= (const float*)d_in[11];
    const float* eta  = (const float*)d_in[12];
    const float* mixr = (const float*)d_in[13];
    const float* mixk = (const float*)d_in[14];
    const float* mixv = (const float*)d_in[15];
    const float* mixg = (const float*)d_in[16];
    const float* gnw  = (const float*)d_in[17];
    const float* gnb  = (const float*)d_in[18];
    float* out = (float*)d_out;

    const int MAIN  = MROWS*CDIM;
    const int STATE = BBAT*HHEAD*64*64;
    const int LASTX = BBAT*CDIM;
    const bool full = out_size >= MAIN + STATE + LASTX;

    if (full) lastx_kernel<<<32,256>>>(x, out + MAIN + STATE);
    wsplit_kernel<<<dim3(1024,5),256>>>(W_r, W_k, W_v, W_g, W_o);
    xsplit_kernel<<<16384,256>>>(x, mixr, mixk, mixv, mixg);
    proj_kernel<<<dim3(8,128,3),128>>>(b_r, b_k, b_v);
    scan_g_kernel<<<1152,128>>>(b_g, decay, eta, full ? (out + MAIN) : nullptr);
    outproj_kernel<<<dim3(8,128),128>>>(b_o, gnw, gnb, out);
}